// round 2
// baseline (speedup 1.0000x reference)
#include <cuda_runtime.h>
#include <math.h>

// Problem constants
#define B_    16
#define CIN   512
#define COUT  512
#define HH    64
#define WW    64
#define SD    512
#define EPSV  1e-8f

// MOD_SCALE = 1/sqrt(512), CONV_SCALE = 1/sqrt(512*9), CS2 = CONV_SCALE^2 = 1/4608
#define MOD_SCALE_F  0.04419417382415922f
#define CONV_SCALE_F 0.014731391274719738f
#define CS2_F        0.00021701388888888888f

// Scratch (allocation-free rule: __device__ globals)
__device__ float g_s[B_ * CIN];        // style modulation s[b][cin]
__device__ float g_wsq[COUT * CIN];    // sum_k W[cout][cin][k]^2
__device__ float g_demod[B_ * COUT];   // demodulation factor

// ---------------------------------------------------------------------------
// 1) s[b][cin] = sum_j style[b][j] * mod_w[cin][j] * MOD_SCALE + mod_b[cin]
//    One warp per output; coalesced over j.
// ---------------------------------------------------------------------------
__global__ void modulate_kernel(const float* __restrict__ style,
                                const float* __restrict__ mw,
                                const float* __restrict__ mb) {
    int warp = (blockIdx.x * blockDim.x + threadIdx.x) >> 5;
    int lane = threadIdx.x & 31;
    if (warp >= B_ * CIN) return;
    int b = warp / CIN, cin = warp % CIN;
    const float* srow = style + (size_t)b * SD;
    const float* wrow = mw + (size_t)cin * SD;
    float sum = 0.f;
    #pragma unroll 4
    for (int j = lane; j < SD; j += 32) sum += srow[j] * wrow[j];
    #pragma unroll
    for (int o = 16; o; o >>= 1) sum += __shfl_xor_sync(0xffffffffu, sum, o);
    if (lane == 0) g_s[warp] = sum * MOD_SCALE_F + mb[cin];
}

// ---------------------------------------------------------------------------
// 2) wsq[cout][cin] = sum over 3x3 of conv_weight^2
// ---------------------------------------------------------------------------
__global__ void wsq_kernel(const float* __restrict__ cw) {
    int idx = blockIdx.x * blockDim.x + threadIdx.x;
    if (idx >= COUT * CIN) return;
    const float* p = cw + (size_t)idx * 9;
    float s = 0.f;
    #pragma unroll
    for (int k = 0; k < 9; k++) s += p[k] * p[k];
    g_wsq[idx] = s;
}

// ---------------------------------------------------------------------------
// 3) demod[b][cout] = rsqrt(CS2 * sum_cin s^2 * wsq + eps). One warp/output.
// ---------------------------------------------------------------------------
__global__ void demod_kernel() {
    int warp = (blockIdx.x * blockDim.x + threadIdx.x) >> 5;
    int lane = threadIdx.x & 31;
    if (warp >= B_ * COUT) return;
    int b = warp / COUT, cout = warp % COUT;
    const float* srow = g_s + (size_t)b * CIN;
    const float* wrow = g_wsq + (size_t)cout * CIN;
    float sum = 0.f;
    #pragma unroll 4
    for (int cin = lane; cin < CIN; cin += 32) {
        float s = srow[cin];
        sum += s * s * wrow[cin];
    }
    #pragma unroll
    for (int o = 16; o; o >>= 1) sum += __shfl_xor_sync(0xffffffffu, sum, o);
    if (lane == 0) g_demod[warp] = rsqrtf(sum * CS2_F + EPSV);
}

// ---------------------------------------------------------------------------
// 4) Shared-weight 3x3 conv with fused input-scale (s) and output-scale
//    (demod * CONV_SCALE).
//    Block: 256 thr -> 32x32 spatial tile x 16 couts, one batch sample.
//    Thread: 2x2 pixels x 16 couts = 64 fp32 accumulators.
//    K-loop over cin in chunks of 8 staged in smem.
// ---------------------------------------------------------------------------
#define TH 32
#define TW 32
#define QC 16
#define CH 8

__global__ __launch_bounds__(256, 2)
void conv_kernel(const float* __restrict__ x,
                 const float* __restrict__ cw,
                 float* __restrict__ out) {
    __shared__ __align__(16) float sin_[CH][34][36];   // halo tile, padded row
    __shared__ __align__(16) float sw_[QC][CH][12];    // 9 weights padded to 12

    const int tid   = threadIdx.x;
    const int b     = blockIdx.z;
    const int cout0 = blockIdx.y * QC;
    const int by0   = (blockIdx.x >> 1) * TH;
    const int bx0   = (blockIdx.x & 1) * TW;
    const int px0   = (tid & 15) * 2;
    const int py0   = (tid >> 4) * 2;

    float acc[QC][2][2];
    #pragma unroll
    for (int q = 0; q < QC; q++)
        #pragma unroll
        for (int i = 0; i < 2; i++)
            #pragma unroll
            for (int j = 0; j < 2; j++) acc[q][i][j] = 0.f;

    for (int cc = 0; cc < CIN; cc += CH) {
        __syncthreads();
        // Stage scaled input tile (zero-padded halo)
        for (int idx = tid; idx < CH * 34 * 34; idx += 256) {
            int ci  = idx / (34 * 34);
            int rem = idx - ci * (34 * 34);
            int r   = rem / 34;
            int c   = rem - r * 34;
            int gy  = by0 + r - 1;
            int gx  = bx0 + c - 1;
            int cin = cc + ci;
            float v = 0.f;
            if ((unsigned)gy < HH && (unsigned)gx < WW)
                v = x[(((size_t)b * CIN + cin) * HH + gy) * WW + gx] * g_s[b * CIN + cin];
            sin_[ci][r][c] = v;
        }
        // Stage weights for 16 couts x 8 cins
        for (int idx = tid; idx < QC * CH * 9; idx += 256) {
            int q   = idx / 72;
            int rem = idx - q * 72;
            int ci  = rem / 9;
            int k   = rem - ci * 9;
            sw_[q][ci][k] = cw[(((size_t)(cout0 + q)) * CIN + cc + ci) * 9 + k];
        }
        __syncthreads();

        #pragma unroll
        for (int ci = 0; ci < CH; ci++) {
            // 4x4 input patch in registers (float2 loads, even offsets -> aligned)
            float xin[4][4];
            #pragma unroll
            for (int i = 0; i < 4; i++) {
                float2 a  = *(const float2*)&sin_[ci][py0 + i][px0];
                float2 b2 = *(const float2*)&sin_[ci][py0 + i][px0 + 2];
                xin[i][0] = a.x;  xin[i][1] = a.y;
                xin[i][2] = b2.x; xin[i][3] = b2.y;
            }
            #pragma unroll
            for (int q = 0; q < QC; q++) {
                // 9 weights via broadcast LDS.128 (warp-uniform address)
                float4 w0 = *(const float4*)&sw_[q][ci][0];
                float4 w1 = *(const float4*)&sw_[q][ci][4];
                float  w8 = sw_[q][ci][8];
                #pragma unroll
                for (int i = 0; i < 2; i++)
                    #pragma unroll
                    for (int j = 0; j < 2; j++) {
                        float s;
                        s  = xin[i    ][j    ] * w0.x;
                        s += xin[i    ][j + 1] * w0.y;
                        s += xin[i    ][j + 2] * w0.z;
                        s += xin[i + 1][j    ] * w0.w;
                        s += xin[i + 1][j + 1] * w1.x;
                        s += xin[i + 1][j + 2] * w1.y;
                        s += xin[i + 2][j    ] * w1.z;
                        s += xin[i + 2][j + 1] * w1.w;
                        s += xin[i + 2][j + 2] * w8;
                        acc[q][i][j] += s;
                    }
            }
        }
    }

    // Epilogue: scale by demod * CONV_SCALE, write float2
    #pragma unroll
    for (int q = 0; q < QC; q++) {
        float d = g_demod[b * COUT + cout0 + q] * CONV_SCALE_F;
        #pragma unroll
        for (int i = 0; i < 2; i++) {
            int oy = by0 + py0 + i;
            float2 v;
            v.x = acc[q][i][0] * d;
            v.y = acc[q][i][1] * d;
            *(float2*)&out[(((size_t)b * COUT + cout0 + q) * HH + oy) * WW + bx0 + px0] = v;
        }
    }
}

// ---------------------------------------------------------------------------
extern "C" void kernel_launch(void* const* d_in, const int* in_sizes, int n_in,
                              void* d_out, int out_size) {
    const float* input  = (const float*)d_in[0];  // [16,512,64,64]
    const float* style  = (const float*)d_in[1];  // [16,512]
    const float* conv_w = (const float*)d_in[2];  // [1,512,512,3,3]
    const float* mod_w  = (const float*)d_in[3];  // [512,512]
    const float* mod_b  = (const float*)d_in[4];  // [512]
    float* out = (float*)d_out;                   // [16,512,64,64]

    modulate_kernel<<<1024, 256>>>(style, mod_w, mod_b);  // 8192 warps
    wsq_kernel<<<1024, 256>>>(conv_w);                    // 262144 threads
    demod_kernel<<<1024, 256>>>();                        // 8192 warps
    conv_kernel<<<dim3(4, 32, 16), 256>>>(input, conv_w, out);
}

// round 6
// speedup vs baseline: 3.0183x; 3.0183x over previous
#include <cuda_runtime.h>
#include <cuda_bf16.h>
#include <cstdint>
#include <math.h>

// ---------------- problem constants ----------------
#define B_    16
#define CIN   512
#define COUT  512
#define HH    64
#define WW    64
#define PIX   4096
#define SD    512
#define EPSV  1e-8f
#define MOD_SCALE_F  0.04419417382415922f   // 1/sqrt(512)
#define CONV_SCALE_F 0.014731391274719738f  // 1/sqrt(512*9)
#define CS2_F        0.00021701388888888888f

// ---------------- tiling ----------------
// CTA: M=128 couts x N=128 pixels, K-chunk = 32 cins, 144 chunks (9 taps x 16)
#define NCH   144
#define ROWB  80                 // padded smem row bytes (64B data + 16B pad)
#define SSTAGE 40960             // Ah|Al|Bh|Bl, each 128*80 = 10240 B
#define AH_O  0
#define AL_O  10240
#define BH_O  20480
#define BL_O  30720
#define DSMEM (3 * SSTAGE)       // 122880 B

// ---------------- scratch ----------------
__device__ float g_s[B_ * CIN];
__device__ float g_wsq[COUT * CIN];
__device__ float g_demod[B_ * COUT];
__device__ __nv_bfloat16 g_xh[(size_t)B_ * PIX * CIN];   // [b][pixel][ci]
__device__ __nv_bfloat16 g_xl[(size_t)B_ * PIX * CIN];
__device__ __nv_bfloat16 g_wh[(size_t)COUT * 9 * CIN];   // [cout][tap][ci]
__device__ __nv_bfloat16 g_wl[(size_t)COUT * 9 * CIN];

// ---------------- PTX helpers (baseline PTX only: sm_80-class) ----------------
__device__ __forceinline__ uint32_t smem_u32(const void* p) {
    uint32_t a;
    asm("{ .reg .u64 t; cvta.to.shared.u64 t, %1; cvt.u32.u64 %0, t; }" : "=r"(a) : "l"(p));
    return a;
}
__device__ __forceinline__ void cpa16(uint32_t dst, const void* src, int srcsize) {
    asm volatile("cp.async.cg.shared.global [%0], [%1], 16, %2;\n"
                 :: "r"(dst), "l"(src), "r"(srcsize) : "memory");
}
#define CP_COMMIT() asm volatile("cp.async.commit_group;" ::: "memory")
#define CP_WAIT1()  asm volatile("cp.async.wait_group 1;" ::: "memory")
#define CP_WAIT0()  asm volatile("cp.async.wait_group 0;" ::: "memory")

#define LDSM4(r, addr) \
    asm volatile("ldmatrix.sync.aligned.m8n8.x4.shared.b16 {%0,%1,%2,%3}, [%4];" \
        : "=r"((r)[0]), "=r"((r)[1]), "=r"((r)[2]), "=r"((r)[3]) : "r"(addr))

#define MMA16816(acc, a, b0, b1) \
    asm volatile("mma.sync.aligned.m16n8k16.row.col.f32.bf16.bf16.f32 " \
        "{%0,%1,%2,%3},{%4,%5,%6,%7},{%8,%9},{%0,%1,%2,%3};" \
        : "+f"((acc)[0]), "+f"((acc)[1]), "+f"((acc)[2]), "+f"((acc)[3]) \
        : "r"((a)[0]), "r"((a)[1]), "r"((a)[2]), "r"((a)[3]), "r"(b0), "r"(b1))

// ---------------- preprocessing kernels ----------------
__global__ void modulate_kernel(const float* __restrict__ style,
                                const float* __restrict__ mw,
                                const float* __restrict__ mb) {
    int warp = (blockIdx.x * blockDim.x + threadIdx.x) >> 5;
    int lane = threadIdx.x & 31;
    if (warp >= B_ * CIN) return;
    int b = warp / CIN, cin = warp % CIN;
    const float* srow = style + (size_t)b * SD;
    const float* wrow = mw + (size_t)cin * SD;
    float sum = 0.f;
    #pragma unroll 4
    for (int j = lane; j < SD; j += 32) sum += srow[j] * wrow[j];
    #pragma unroll
    for (int o = 16; o; o >>= 1) sum += __shfl_xor_sync(0xffffffffu, sum, o);
    if (lane == 0) g_s[warp] = sum * MOD_SCALE_F + mb[cin];
}

__global__ void wsq_kernel(const float* __restrict__ cw) {
    int idx = blockIdx.x * blockDim.x + threadIdx.x;
    if (idx >= COUT * CIN) return;
    const float* p = cw + (size_t)idx * 9;
    float s = 0.f;
    #pragma unroll
    for (int k = 0; k < 9; k++) s += p[k] * p[k];
    g_wsq[idx] = s;
}

__global__ void demod_kernel() {
    int warp = (blockIdx.x * blockDim.x + threadIdx.x) >> 5;
    int lane = threadIdx.x & 31;
    if (warp >= B_ * COUT) return;
    int b = warp / COUT, cout = warp % COUT;
    const float* srow = g_s + (size_t)b * CIN;
    const float* wrow = g_wsq + (size_t)cout * CIN;
    float sum = 0.f;
    #pragma unroll 4
    for (int cin = lane; cin < CIN; cin += 32) {
        float s = srow[cin];
        sum += s * s * wrow[cin];
    }
    #pragma unroll
    for (int o = 16; o; o >>= 1) sum += __shfl_xor_sync(0xffffffffu, sum, o);
    if (lane == 0) g_demod[warp] = rsqrtf(sum * CS2_F + EPSV);
}

// weights: [cout][cin][tap] -> [cout][tap][cin], hi/lo bf16 split
__global__ void wprep_kernel(const float* __restrict__ cw) {
    int idx = blockIdx.x * blockDim.x + threadIdx.x;
    if (idx >= COUT * 9 * CIN) return;
    int cout = idx / (9 * CIN);
    int r = idx - cout * (9 * CIN);
    int tap = r / CIN;
    int ci = r - tap * CIN;
    float v = cw[((size_t)cout * CIN + ci) * 9 + tap];
    __nv_bfloat16 hi = __float2bfloat16(v);
    __nv_bfloat16 lo = __float2bfloat16(v - __bfloat162float(hi));
    g_wh[idx] = hi;
    g_wl[idx] = lo;
}

// input: [b][ci][p] * s[b][ci] -> channel-last [b][p][ci], hi/lo split
__global__ __launch_bounds__(256) void xprep_kernel(const float* __restrict__ x) {
    __shared__ float tile[64][65];
    int b = blockIdx.z, ci0 = blockIdx.y * 64, p0 = blockIdx.x * 64;
    int tid = threadIdx.x;
    int j = tid & 63, i0 = tid >> 6;
    #pragma unroll
    for (int ii = 0; ii < 16; ii++) {
        int ci = i0 + ii * 4;
        float s = g_s[b * CIN + ci0 + ci];
        tile[ci][j] = x[((size_t)(b * CIN + ci0 + ci)) * PIX + p0 + j] * s;
    }
    __syncthreads();
    #pragma unroll
    for (int ii = 0; ii < 16; ii++) {
        int pl = i0 + ii * 4;
        float v = tile[j][pl];
        __nv_bfloat16 hi = __float2bfloat16(v);
        __nv_bfloat16 lo = __float2bfloat16(v - __bfloat162float(hi));
        size_t o = ((size_t)b * PIX + p0 + pl) * CIN + ci0 + j;
        g_xh[o] = hi;
        g_xl[o] = lo;
    }
}

// ---------------- main HMMA implicit-GEMM conv ----------------
__global__ __launch_bounds__(256, 1) void conv_kernel(float* __restrict__ out) {
    extern __shared__ char smem[];
    const uint32_t sb = smem_u32(smem);
    const int tid = threadIdx.x;
    const int ptile = blockIdx.x;            // 32 pixel tiles (128 px = 2 rows)
    const int cout0 = blockIdx.y * 128;      // 4 cout tiles
    const int b = blockIdx.z;
    const int warp = tid >> 5, lane = tid & 31;
    const int mw = warp & 1;                 // 2 m-warps (64 couts each)
    const int nw = warp >> 1;                // 4 n-warps (32 pixels each)

    // staging coords: 2 threads per row (halves of 64B)
    const int rs = tid >> 1;                 // row 0..127
    const int hs = tid & 1;                  // 32B half
    const int py0 = (ptile * 128 + rs) >> 6; // image row of pixel rs
    const int px0 = rs & 63;

    float acc[4][4][4];
    #pragma unroll
    for (int mt = 0; mt < 4; mt++)
        #pragma unroll
        for (int nt = 0; nt < 4; nt++)
            #pragma unroll
            for (int r = 0; r < 4; r++) acc[mt][nt][r] = 0.f;

    // ---- async fetch of chunk i into stage i%3 ----
    #define FETCH(i) do {                                                        \
        int _tap = (i) >> 4;                                                     \
        int _kc  = ((i) & 15) << 5;                                              \
        uint32_t _stb = sb + ((i) % 3) * SSTAGE;                                 \
        int _dy = _tap / 3, _dx = _tap - _dy * 3;                                \
        size_t _wo = ((size_t)(cout0 + rs) * 9 + _tap) * CIN + _kc + hs * 16;    \
        uint32_t _ad = _stb + rs * ROWB + hs * 32;                               \
        cpa16(_ad + AH_O,      g_wh + _wo,     16);                              \
        cpa16(_ad + AH_O + 16, g_wh + _wo + 8, 16);                              \
        cpa16(_ad + AL_O,      g_wl + _wo,     16);                              \
        cpa16(_ad + AL_O + 16, g_wl + _wo + 8, 16);                              \
        int _py = py0 + _dy - 1, _px = px0 + _dx - 1;                            \
        bool _ok = ((unsigned)_py < HH) && ((unsigned)_px < WW);                 \
        size_t _xo = _ok ? (((size_t)(b * PIX + _py * WW + _px)) * CIN + _kc + hs * 16) : 0; \
        int _sz = _ok ? 16 : 0;                                                  \
        cpa16(_ad + BH_O,      g_xh + _xo,     _sz);                             \
        cpa16(_ad + BH_O + 16, g_xh + _xo + 8, _sz);                             \
        cpa16(_ad + BL_O,      g_xl + _xo,     _sz);                             \
        cpa16(_ad + BL_O + 16, g_xl + _xo + 8, _sz);                             \
        CP_COMMIT();                                                             \
    } while (0)

    FETCH(0);
    FETCH(1);

    // per-lane ldmatrix addresses (constant part)
    const int am = mw * 64 + (lane & 7) + ((lane >> 3) & 1) * 8;   // + mt*16
    const uint32_t akb = ((lane >> 4) & 1) * 16;                   // + kk*32
    const int bn = nw * 32 + ((lane >> 4) & 1) * 8 + (lane & 7);   // + pr*16
    const uint32_t bkb = ((lane >> 3) & 1) * 16;                   // + kk*32

    for (int i = 0; i < NCH; i++) {
        if (i < NCH - 1) CP_WAIT1(); else CP_WAIT0();
        __syncthreads();
        if (i + 2 < NCH) FETCH(i + 2);

        const uint32_t stb = sb + (i % 3) * SSTAGE;
        #pragma unroll
        for (int kk = 0; kk < 2; kk++) {
            uint32_t ah[4][4], al[4][4], bh[2][4], bl[2][4];
            #pragma unroll
            for (int mt = 0; mt < 4; mt++) {
                uint32_t a = stb + (uint32_t)(am + mt * 16) * ROWB + kk * 32 + akb;
                LDSM4(ah[mt], a + AH_O);
                LDSM4(al[mt], a + AL_O);
            }
            #pragma unroll
            for (int pr = 0; pr < 2; pr++) {
                uint32_t a = stb + (uint32_t)(bn + pr * 16) * ROWB + kk * 32 + bkb;
                LDSM4(bh[pr], a + BH_O);
                LDSM4(bl[pr], a + BL_O);
            }
            #pragma unroll
            for (int mt = 0; mt < 4; mt++)
                #pragma unroll
                for (int nt = 0; nt < 4; nt++) {
                    const int pr = nt >> 1, o = (nt & 1) * 2;
                    MMA16816(acc[mt][nt], ah[mt], bh[pr][o], bh[pr][o + 1]);
                    MMA16816(acc[mt][nt], al[mt], bh[pr][o], bh[pr][o + 1]);
                    MMA16816(acc[mt][nt], ah[mt], bl[pr][o], bl[pr][o + 1]);
                }
        }
    }

    // ---- epilogue: scale by demod*CONV_SCALE, write float2 ----
    const int r4 = lane >> 2, t4 = lane & 3;
    #pragma unroll
    for (int mt = 0; mt < 4; mt++) {
        const int c0 = cout0 + mw * 64 + mt * 16 + r4;
        const float d0 = g_demod[b * COUT + c0] * CONV_SCALE_F;
        const float d1 = g_demod[b * COUT + c0 + 8] * CONV_SCALE_F;
        #pragma unroll
        for (int nt = 0; nt < 4; nt++) {
            const int pix = ptile * 128 + nw * 32 + nt * 8 + t4 * 2;
            float* p0 = out + ((size_t)(b * COUT + c0)) * PIX + pix;
            float* p1 = out + ((size_t)(b * COUT + c0 + 8)) * PIX + pix;
            float2 v0, v1;
            v0.x = acc[mt][nt][0] * d0; v0.y = acc[mt][nt][1] * d0;
            v1.x = acc[mt][nt][2] * d1; v1.y = acc[mt][nt][3] * d1;
            *(float2*)p0 = v0;
            *(float2*)p1 = v1;
        }
    }
}

// ---------------- launch ----------------
extern "C" void kernel_launch(void* const* d_in, const int* in_sizes, int n_in,
                              void* d_out, int out_size) {
    const float* input  = (const float*)d_in[0];  // [16,512,64,64]
    const float* style  = (const float*)d_in[1];  // [16,512]
    const float* conv_w = (const float*)d_in[2];  // [1,512,512,3,3]
    const float* mod_w  = (const float*)d_in[3];  // [512,512]
    const float* mod_b  = (const float*)d_in[4];  // [512]
    float* out = (float*)d_out;                   // [16,512,64,64]

    modulate_kernel<<<1024, 256>>>(style, mod_w, mod_b);
    wsq_kernel<<<1024, 256>>>(conv_w);
    demod_kernel<<<1024, 256>>>();
    wprep_kernel<<<(COUT * 9 * CIN + 255) / 256, 256>>>(conv_w);
    xprep_kernel<<<dim3(PIX / 64, CIN / 64, B_), 256>>>(input);

    cudaFuncSetAttribute(conv_kernel, cudaFuncAttributeMaxDynamicSharedMemorySize, DSMEM);
    conv_kernel<<<dim3(32, 4, B_), 256, DSMEM>>>(out);
}

// round 8
// speedup vs baseline: 5.5885x; 1.8515x over previous
#include <cuda_runtime.h>
#include <cuda_fp16.h>
#include <cstdint>
#include <math.h>

// ---------------- problem constants ----------------
#define B_    16
#define CIN   512
#define COUT  512
#define HH    64
#define WW    64
#define PIX   4096
#define SD    512
#define EPSV  1e-8f
#define MOD_SCALE_F  0.04419417382415922f   // 1/sqrt(512)
#define CONV_SCALE_F 0.014731391274719738f  // 1/sqrt(512*9)
#define CS2_F        0.00021701388888888888f

// ---------------- tiling ----------------
// CTA: M=128 couts x N=128 pixels, K-chunk = 32 cins, 144 chunks (9 taps x 16)
#define NCH   144
#define ROWB  80                 // padded smem row bytes (64B data + 16B pad)
#define A_O   0
#define B_O   10240
#define SSTAGE 20480             // A 10240 | B 10240
#define NSTG  4
#define DSMEM (NSTG * SSTAGE)    // 81920 B

// ---------------- scratch ----------------
__device__ float g_s[B_ * CIN];
__device__ float g_wsq[COUT * CIN];
__device__ float g_demod[B_ * COUT];
__device__ __half g_xh[(size_t)B_ * PIX * CIN];   // [b][pixel][ci]  (x * s, fp16)
__device__ __half g_wh[(size_t)COUT * 9 * CIN];   // [cout][tap][ci] (fp16)

// ---------------- PTX helpers (baseline PTX, sm_80-class) ----------------
__device__ __forceinline__ uint32_t smem_u32(const void* p) {
    uint32_t a;
    asm("{ .reg .u64 t; cvta.to.shared.u64 t, %1; cvt.u32.u64 %0, t; }" : "=r"(a) : "l"(p));
    return a;
}
__device__ __forceinline__ void cpa16(uint32_t dst, const void* src, int srcsize) {
    asm volatile("cp.async.cg.shared.global [%0], [%1], 16, %2;\n"
                 :: "r"(dst), "l"(src), "r"(srcsize) : "memory");
}
#define CP_COMMIT() asm volatile("cp.async.commit_group;" ::: "memory")
#define CP_WAIT2()  asm volatile("cp.async.wait_group 2;" ::: "memory")
#define CP_WAIT1()  asm volatile("cp.async.wait_group 1;" ::: "memory")
#define CP_WAIT0()  asm volatile("cp.async.wait_group 0;" ::: "memory")

#define LDSM4(r, addr) \
    asm volatile("ldmatrix.sync.aligned.m8n8.x4.shared.b16 {%0,%1,%2,%3}, [%4];" \
        : "=r"((r)[0]), "=r"((r)[1]), "=r"((r)[2]), "=r"((r)[3]) : "r"(addr))

#define MMA16816(acc, a, b0, b1) \
    asm volatile("mma.sync.aligned.m16n8k16.row.col.f32.f16.f16.f32 " \
        "{%0,%1,%2,%3},{%4,%5,%6,%7},{%8,%9},{%0,%1,%2,%3};" \
        : "+f"((acc)[0]), "+f"((acc)[1]), "+f"((acc)[2]), "+f"((acc)[3]) \
        : "r"((a)[0]), "r"((a)[1]), "r"((a)[2]), "r"((a)[3]), "r"(b0), "r"(b1))

// ---------------- preprocessing kernels ----------------
__global__ void modulate_kernel(const float* __restrict__ style,
                                const float* __restrict__ mw,
                                const float* __restrict__ mb) {
    int warp = (blockIdx.x * blockDim.x + threadIdx.x) >> 5;
    int lane = threadIdx.x & 31;
    if (warp >= B_ * CIN) return;
    int b = warp / CIN, cin = warp % CIN;
    const float* srow = style + (size_t)b * SD;
    const float* wrow = mw + (size_t)cin * SD;
    float sum = 0.f;
    #pragma unroll 4
    for (int j = lane; j < SD; j += 32) sum += srow[j] * wrow[j];
    #pragma unroll
    for (int o = 16; o; o >>= 1) sum += __shfl_xor_sync(0xffffffffu, sum, o);
    if (lane == 0) g_s[warp] = sum * MOD_SCALE_F + mb[cin];
}

// weights: per (cout, cin) thread: read 9 taps, write fp16 [cout][tap][cin] + wsq
__global__ void wprep_kernel(const float* __restrict__ cw) {
    int idx = blockIdx.x * blockDim.x + threadIdx.x;
    if (idx >= COUT * CIN) return;
    int cout = idx / CIN;
    int ci = idx - cout * CIN;
    const float* p = cw + (size_t)idx * 9;
    float sq = 0.f;
    #pragma unroll
    for (int k = 0; k < 9; k++) {
        float v = p[k];
        sq += v * v;
        g_wh[((size_t)cout * 9 + k) * CIN + ci] = __float2half_rn(v);
    }
    g_wsq[idx] = sq;
}

__global__ void demod_kernel() {
    int warp = (blockIdx.x * blockDim.x + threadIdx.x) >> 5;
    int lane = threadIdx.x & 31;
    if (warp >= B_ * COUT) return;
    int b = warp / COUT, cout = warp % COUT;
    const float* srow = g_s + (size_t)b * CIN;
    const float* wrow = g_wsq + (size_t)cout * CIN;
    float sum = 0.f;
    #pragma unroll 4
    for (int cin = lane; cin < CIN; cin += 32) {
        float s = srow[cin];
        sum += s * s * wrow[cin];
    }
    #pragma unroll
    for (int o = 16; o; o >>= 1) sum += __shfl_xor_sync(0xffffffffu, sum, o);
    if (lane == 0) g_demod[warp] = rsqrtf(sum * CS2_F + EPSV);
}

// input: [b][ci][p] * s[b][ci] -> channel-last fp16 [b][p][ci]
__global__ __launch_bounds__(256) void xprep_kernel(const float* __restrict__ x) {
    __shared__ float tile[64][65];
    int b = blockIdx.z, ci0 = blockIdx.y * 64, p0 = blockIdx.x * 64;
    int tid = threadIdx.x;
    int j = tid & 63, i0 = tid >> 6;
    #pragma unroll
    for (int ii = 0; ii < 16; ii++) {
        int ci = i0 + ii * 4;
        float s = g_s[b * CIN + ci0 + ci];
        tile[ci][j] = x[((size_t)(b * CIN + ci0 + ci)) * PIX + p0 + j] * s;
    }
    __syncthreads();
    #pragma unroll
    for (int ii = 0; ii < 16; ii++) {
        int pl = i0 + ii * 4;
        g_xh[((size_t)b * PIX + p0 + pl) * CIN + ci0 + j] = __float2half_rn(tile[j][pl]);
    }
}

// ---------------- main HMMA implicit-GEMM conv (single fp16) ----------------
__global__ __launch_bounds__(256, 1) void conv_kernel(float* __restrict__ out) {
    extern __shared__ char smem[];
    const uint32_t sb = smem_u32(smem);
    const int tid = threadIdx.x;
    const int ptile = blockIdx.x;            // 32 pixel tiles (128 px = 2 rows)
    const int cout0 = blockIdx.y * 128;      // 4 cout tiles
    const int b = blockIdx.z;
    const int warp = tid >> 5, lane = tid & 31;
    const int mw = warp & 1;                 // 2 m-warps (64 couts each)
    const int nw = warp >> 1;                // 4 n-warps (32 pixels each)

    // staging: threads 0-127 stage A row rs; threads 128-255 stage B row rs
    const int rs = tid & 127;
    const bool isA = tid < 128;
    const int py0 = (ptile * 128 + rs) >> 6;
    const int px0 = rs & 63;

    float acc[4][4][4];
    #pragma unroll
    for (int mt = 0; mt < 4; mt++)
        #pragma unroll
        for (int nt = 0; nt < 4; nt++)
            #pragma unroll
            for (int r = 0; r < 4; r++) acc[mt][nt][r] = 0.f;

    #define FETCH(i) do {                                                        \
        int _tap = (i) >> 4;                                                     \
        int _kc  = ((i) & 15) << 5;                                              \
        uint32_t _stb = sb + ((i) % NSTG) * SSTAGE;                              \
        if (isA) {                                                               \
            const __half* _as = g_wh + ((size_t)(cout0 + rs) * 9 + _tap) * CIN + _kc; \
            uint32_t _ad = _stb + A_O + rs * ROWB;                               \
            cpa16(_ad,      _as,      16);                                       \
            cpa16(_ad + 16, _as + 8,  16);                                       \
            cpa16(_ad + 32, _as + 16, 16);                                       \
            cpa16(_ad + 48, _as + 24, 16);                                       \
        } else {                                                                 \
            int _dy = _tap / 3, _dx = _tap - _dy * 3;                            \
            int _py = py0 + _dy - 1, _px = px0 + _dx - 1;                        \
            bool _ok = ((unsigned)_py < HH) && ((unsigned)_px < WW);             \
            size_t _xo = _ok ? (((size_t)(b * PIX + _py * WW + _px)) * CIN + _kc) : 0; \
            int _sz = _ok ? 16 : 0;                                              \
            const __half* _bs = g_xh + _xo;                                      \
            uint32_t _bd = _stb + B_O + rs * ROWB;                               \
            cpa16(_bd,      _bs,      _sz);                                      \
            cpa16(_bd + 16, _bs + 8,  _sz);                                      \
            cpa16(_bd + 32, _bs + 16, _sz);                                      \
            cpa16(_bd + 48, _bs + 24, _sz);                                      \
        }                                                                        \
        CP_COMMIT();                                                             \
    } while (0)

    FETCH(0);
    FETCH(1);
    FETCH(2);

    // per-lane ldmatrix address components (same verified layout as R4)
    const int am = mw * 64 + (lane & 7) + ((lane >> 3) & 1) * 8;   // + mt*16
    const uint32_t akb = ((lane >> 4) & 1) * 16;                   // + kk*32
    const int bn = nw * 32 + ((lane >> 4) & 1) * 8 + (lane & 7);   // + pr*16
    const uint32_t bkb = ((lane >> 3) & 1) * 16;                   // + kk*32

    for (int i = 0; i < NCH; i++) {
        if (i <= NCH - 3)      CP_WAIT2();
        else if (i == NCH - 2) CP_WAIT1();
        else                   CP_WAIT0();
        __syncthreads();
        if (i + 3 < NCH) FETCH(i + 3);

        const uint32_t stb = sb + (i % NSTG) * SSTAGE;
        #pragma unroll
        for (int kk = 0; kk < 2; kk++) {
            uint32_t a[4][4], bfr[2][4];
            #pragma unroll
            for (int mt = 0; mt < 4; mt++)
                LDSM4(a[mt], stb + A_O + (uint32_t)(am + mt * 16) * ROWB + kk * 32 + akb);
            #pragma unroll
            for (int pr = 0; pr < 2; pr++)
                LDSM4(bfr[pr], stb + B_O + (uint32_t)(bn + pr * 16) * ROWB + kk * 32 + bkb);
            #pragma unroll
            for (int mt = 0; mt < 4; mt++)
                #pragma unroll
                for (int nt = 0; nt < 4; nt++) {
                    const int pr = nt >> 1, o = (nt & 1) * 2;
                    MMA16816(acc[mt][nt], a[mt], bfr[pr][o], bfr[pr][o + 1]);
                }
        }
    }

    // ---- epilogue: scale by demod*CONV_SCALE, write float2 ----
    const int r4 = lane >> 2, t4 = lane & 3;
    #pragma unroll
    for (int mt = 0; mt < 4; mt++) {
        const int c0 = cout0 + mw * 64 + mt * 16 + r4;
        const float d0 = g_demod[b * COUT + c0] * CONV_SCALE_F;
        const float d1 = g_demod[b * COUT + c0 + 8] * CONV_SCALE_F;
        #pragma unroll
        for (int nt = 0; nt < 4; nt++) {
            const int pix = ptile * 128 + nw * 32 + nt * 8 + t4 * 2;
            float* p0 = out + ((size_t)(b * COUT + c0)) * PIX + pix;
            float* p1 = out + ((size_t)(b * COUT + c0 + 8)) * PIX + pix;
            float2 v0, v1;
            v0.x = acc[mt][nt][0] * d0; v0.y = acc[mt][nt][1] * d0;
            v1.x = acc[mt][nt][2] * d1; v1.y = acc[mt][nt][3] * d1;
            *(float2*)p0 = v0;
            *(float2*)p1 = v1;
        }
    }
}

// ---------------- launch ----------------
extern "C" void kernel_launch(void* const* d_in, const int* in_sizes, int n_in,
                              void* d_out, int out_size) {
    const float* input  = (const float*)d_in[0];  // [16,512,64,64]
    const float* style  = (const float*)d_in[1];  // [16,512]
    const float* conv_w = (const float*)d_in[2];  // [1,512,512,3,3]
    const float* mod_w  = (const float*)d_in[3];  // [512,512]
    const float* mod_b  = (const float*)d_in[4];  // [512]
    float* out = (float*)d_out;                   // [16,512,64,64]

    modulate_kernel<<<1024, 256>>>(style, mod_w, mod_b);
    wprep_kernel<<<(COUT * CIN + 255) / 256, 256>>>(conv_w);
    demod_kernel<<<1024, 256>>>();
    xprep_kernel<<<dim3(PIX / 64, CIN / 64, B_), 256>>>(input);

    cudaFuncSetAttribute(conv_kernel, cudaFuncAttributeMaxDynamicSharedMemorySize, DSMEM);
    conv_kernel<<<dim3(32, 4, B_), 256, DSMEM>>>(out);
}

// round 9
// speedup vs baseline: 6.5202x; 1.1667x over previous
#include <cuda_runtime.h>
#include <cuda_fp16.h>
#include <cstdint>
#include <math.h>

// ---------------- problem constants ----------------
#define B_    16
#define CIN   512
#define COUT  512
#define HH    64
#define WW    64
#define PIX   4096
#define SD    512
#define EPSV  1e-8f
#define MOD_SCALE_F  0.04419417382415922f   // 1/sqrt(512)
#define CONV_SCALE_F 0.014731391274719738f  // 1/sqrt(512*9)
#define CS2_F        0.00021701388888888888f

// ---------------- tiling ----------------
// CTA: M=128 couts x N=256 pixels (4 image rows), K-chunk=32 cins, 144 chunks
#define NCH   144
#define ROWB  80                 // padded smem row bytes (64B data + 16B pad)
#define A_O   0
#define B_O   10240              // A: 128 rows * 80B
#define SSTAGE 30720             // A 10240 | B 20480 (256 rows * 80B)
#define NSTG  4
#define DSMEM (NSTG * SSTAGE)    // 122880 B

// ---------------- scratch ----------------
__device__ float g_s[B_ * CIN];
__device__ float g_wsq[COUT * CIN];
__device__ float g_demod[B_ * COUT];
__device__ __half g_xh[(size_t)B_ * PIX * CIN];   // [b][pixel][ci]  (x * s, fp16)
__device__ __half g_wh[(size_t)COUT * 9 * CIN];   // [cout][tap][ci] (fp16)

// ---------------- PTX helpers (baseline PTX, sm_80-class) ----------------
__device__ __forceinline__ uint32_t smem_u32(const void* p) {
    uint32_t a;
    asm("{ .reg .u64 t; cvta.to.shared.u64 t, %1; cvt.u32.u64 %0, t; }" : "=r"(a) : "l"(p));
    return a;
}
__device__ __forceinline__ void cpa16(uint32_t dst, const void* src, int srcsize) {
    asm volatile("cp.async.cg.shared.global [%0], [%1], 16, %2;\n"
                 :: "r"(dst), "l"(src), "r"(srcsize) : "memory");
}
#define CP_COMMIT() asm volatile("cp.async.commit_group;" ::: "memory")
#define CP_WAIT2()  asm volatile("cp.async.wait_group 2;" ::: "memory")
#define CP_WAIT1()  asm volatile("cp.async.wait_group 1;" ::: "memory")
#define CP_WAIT0()  asm volatile("cp.async.wait_group 0;" ::: "memory")

#define LDSM4(r, addr) \
    asm volatile("ldmatrix.sync.aligned.m8n8.x4.shared.b16 {%0,%1,%2,%3}, [%4];" \
        : "=r"((r)[0]), "=r"((r)[1]), "=r"((r)[2]), "=r"((r)[3]) : "r"(addr))

#define MMA16816(acc, a, b0, b1) \
    asm volatile("mma.sync.aligned.m16n8k16.row.col.f32.f16.f16.f32 " \
        "{%0,%1,%2,%3},{%4,%5,%6,%7},{%8,%9},{%0,%1,%2,%3};" \
        : "+f"((acc)[0]), "+f"((acc)[1]), "+f"((acc)[2]), "+f"((acc)[3]) \
        : "r"((a)[0]), "r"((a)[1]), "r"((a)[2]), "r"((a)[3]), "r"(b0), "r"(b1))

// ---------------- preprocessing kernels ----------------
__global__ void modulate_kernel(const float* __restrict__ style,
                                const float* __restrict__ mw,
                                const float* __restrict__ mb) {
    int warp = (blockIdx.x * blockDim.x + threadIdx.x) >> 5;
    int lane = threadIdx.x & 31;
    if (warp >= B_ * CIN) return;
    int b = warp / CIN, cin = warp % CIN;
    const float* srow = style + (size_t)b * SD;
    const float* wrow = mw + (size_t)cin * SD;
    float sum = 0.f;
    #pragma unroll 4
    for (int j = lane; j < SD; j += 32) sum += srow[j] * wrow[j];
    #pragma unroll
    for (int o = 16; o; o >>= 1) sum += __shfl_xor_sync(0xffffffffu, sum, o);
    if (lane == 0) g_s[warp] = sum * MOD_SCALE_F + mb[cin];
}

// weights: per (cout, cin) thread: read 9 taps, write fp16 [cout][tap][cin] + wsq
__global__ void wprep_kernel(const float* __restrict__ cw) {
    int idx = blockIdx.x * blockDim.x + threadIdx.x;
    if (idx >= COUT * CIN) return;
    int cout = idx / CIN;
    int ci = idx - cout * CIN;
    const float* p = cw + (size_t)idx * 9;
    float sq = 0.f;
    #pragma unroll
    for (int k = 0; k < 9; k++) {
        float v = p[k];
        sq += v * v;
        g_wh[((size_t)cout * 9 + k) * CIN + ci] = __float2half_rn(v);
    }
    g_wsq[idx] = sq;
}

__global__ void demod_kernel() {
    int warp = (blockIdx.x * blockDim.x + threadIdx.x) >> 5;
    int lane = threadIdx.x & 31;
    if (warp >= B_ * COUT) return;
    int b = warp / COUT, cout = warp % COUT;
    const float* srow = g_s + (size_t)b * CIN;
    const float* wrow = g_wsq + (size_t)cout * CIN;
    float sum = 0.f;
    #pragma unroll 4
    for (int cin = lane; cin < CIN; cin += 32) {
        float s = srow[cin];
        sum += s * s * wrow[cin];
    }
    #pragma unroll
    for (int o = 16; o; o >>= 1) sum += __shfl_xor_sync(0xffffffffu, sum, o);
    if (lane == 0) g_demod[warp] = rsqrtf(sum * CS2_F + EPSV);
}

// input: [b][ci][p] * s[b][ci] -> channel-last fp16 [b][p][ci]
__global__ __launch_bounds__(256) void xprep_kernel(const float* __restrict__ x) {
    __shared__ float tile[64][65];
    int b = blockIdx.z, ci0 = blockIdx.y * 64, p0 = blockIdx.x * 64;
    int tid = threadIdx.x;
    int j = tid & 63, i0 = tid >> 6;
    #pragma unroll
    for (int ii = 0; ii < 16; ii++) {
        int ci = i0 + ii * 4;
        float s = g_s[b * CIN + ci0 + ci];
        tile[ci][j] = x[((size_t)(b * CIN + ci0 + ci)) * PIX + p0 + j] * s;
    }
    __syncthreads();
    #pragma unroll
    for (int ii = 0; ii < 16; ii++) {
        int pl = i0 + ii * 4;
        g_xh[((size_t)b * PIX + p0 + pl) * CIN + ci0 + j] = __float2half_rn(tile[j][pl]);
    }
}

// ---------------- main HMMA implicit-GEMM conv (128x256 CTA, 64x64 warp) ----
__global__ __launch_bounds__(256, 1) void conv_kernel(float* __restrict__ out) {
    extern __shared__ char smem[];
    const uint32_t sb = smem_u32(smem);
    const int tid = threadIdx.x;
    const int ptile = blockIdx.x;            // 16 pixel tiles (256 px = 4 rows)
    const int cout0 = blockIdx.y * 128;      // 4 cout tiles
    const int b = blockIdx.z;
    const int warp = tid >> 5, lane = tid & 31;
    const int mw = warp & 1;                 // 2 m-warps (64 couts each)
    const int nw = warp >> 1;                // 4 n-warps (64 pixels each)

    // staging: every thread stages B row tid; threads 0-127 also stage A row tid
    const bool isA = tid < 128;
    const int py0 = (ptile * 256 + tid) >> 6;
    const int px0 = tid & 63;

    float acc[4][8][4];
    #pragma unroll
    for (int mt = 0; mt < 4; mt++)
        #pragma unroll
        for (int nt = 0; nt < 8; nt++)
            #pragma unroll
            for (int r = 0; r < 4; r++) acc[mt][nt][r] = 0.f;

    #define FETCH(i) do {                                                        \
        int _tap = (i) >> 4;                                                     \
        int _kc  = ((i) & 15) << 5;                                              \
        uint32_t _stb = sb + ((i) % NSTG) * SSTAGE;                              \
        if (isA) {                                                               \
            const __half* _as = g_wh + ((size_t)(cout0 + tid) * 9 + _tap) * CIN + _kc; \
            uint32_t _ad = _stb + A_O + tid * ROWB;                              \
            cpa16(_ad,      _as,      16);                                       \
            cpa16(_ad + 16, _as + 8,  16);                                       \
            cpa16(_ad + 32, _as + 16, 16);                                       \
            cpa16(_ad + 48, _as + 24, 16);                                       \
        }                                                                        \
        {                                                                        \
            int _dy = _tap / 3, _dx = _tap - _dy * 3;                            \
            int _py = py0 + _dy - 1, _px = px0 + _dx - 1;                        \
            bool _ok = ((unsigned)_py < HH) && ((unsigned)_px < WW);             \
            size_t _xo = _ok ? (((size_t)(b * PIX + _py * WW + _px)) * CIN + _kc) : 0; \
            int _sz = _ok ? 16 : 0;                                              \
            const __half* _bs = g_xh + _xo;                                      \
            uint32_t _bd = _stb + B_O + tid * ROWB;                              \
            cpa16(_bd,      _bs,      _sz);                                      \
            cpa16(_bd + 16, _bs + 8,  _sz);                                      \
            cpa16(_bd + 32, _bs + 16, _sz);                                      \
            cpa16(_bd + 48, _bs + 24, _sz);                                      \
        }                                                                        \
        CP_COMMIT();                                                             \
    } while (0)

    FETCH(0);
    FETCH(1);
    FETCH(2);

    // per-lane ldmatrix address components (proven layout, extended ranges)
    const int am = mw * 64 + (lane & 7) + ((lane >> 3) & 1) * 8;   // + mt*16
    const uint32_t akb = ((lane >> 4) & 1) * 16;                   // + kk*32
    const int bn = nw * 64 + ((lane >> 4) & 1) * 8 + (lane & 7);   // + pr*16
    const uint32_t bkb = ((lane >> 3) & 1) * 16;                   // + kk*32

    for (int i = 0; i < NCH; i++) {
        if (i <= NCH - 3)      CP_WAIT2();
        else if (i == NCH - 2) CP_WAIT1();
        else                   CP_WAIT0();
        __syncthreads();
        if (i + 3 < NCH) FETCH(i + 3);

        const uint32_t stb = sb + (i % NSTG) * SSTAGE;
        #pragma unroll
        for (int kk = 0; kk < 2; kk++) {
            uint32_t a[4][4], bfr[4][4];
            #pragma unroll
            for (int mt = 0; mt < 4; mt++)
                LDSM4(a[mt], stb + A_O + (uint32_t)(am + mt * 16) * ROWB + kk * 32 + akb);
            #pragma unroll
            for (int pr = 0; pr < 4; pr++)
                LDSM4(bfr[pr], stb + B_O + (uint32_t)(bn + pr * 16) * ROWB + kk * 32 + bkb);
            #pragma unroll
            for (int mt = 0; mt < 4; mt++)
                #pragma unroll
                for (int nt = 0; nt < 8; nt++) {
                    const int pr = nt >> 1, o = (nt & 1) * 2;
                    MMA16816(acc[mt][nt], a[mt], bfr[pr][o], bfr[pr][o + 1]);
                }
        }
    }

    // ---- epilogue: scale by demod*CONV_SCALE, write float2 ----
    const int r4 = lane >> 2, t4 = lane & 3;
    #pragma unroll
    for (int mt = 0; mt < 4; mt++) {
        const int c0 = cout0 + mw * 64 + mt * 16 + r4;
        const float d0 = g_demod[b * COUT + c0] * CONV_SCALE_F;
        const float d1 = g_demod[b * COUT + c0 + 8] * CONV_SCALE_F;
        #pragma unroll
        for (int nt = 0; nt < 8; nt++) {
            const int pix = ptile * 256 + nw * 64 + nt * 8 + t4 * 2;
            float* p0 = out + ((size_t)(b * COUT + c0)) * PIX + pix;
            float* p1 = out + ((size_t)(b * COUT + c0 + 8)) * PIX + pix;
            float2 v0, v1;
            v0.x = acc[mt][nt][0] * d0; v0.y = acc[mt][nt][1] * d0;
            v1.x = acc[mt][nt][2] * d1; v1.y = acc[mt][nt][3] * d1;
            *(float2*)p0 = v0;
            *(float2*)p1 = v1;
        }
    }
}

// ---------------- launch ----------------
extern "C" void kernel_launch(void* const* d_in, const int* in_sizes, int n_in,
                              void* d_out, int out_size) {
    const float* input  = (const float*)d_in[0];  // [16,512,64,64]
    const float* style  = (const float*)d_in[1];  // [16,512]
    const float* conv_w = (const float*)d_in[2];  // [1,512,512,3,3]
    const float* mod_w  = (const float*)d_in[3];  // [512,512]
    const float* mod_b  = (const float*)d_in[4];  // [512]
    float* out = (float*)d_out;                   // [16,512,64,64]

    modulate_kernel<<<1024, 256>>>(style, mod_w, mod_b);
    wprep_kernel<<<(COUT * CIN + 255) / 256, 256>>>(conv_w);
    demod_kernel<<<1024, 256>>>();
    xprep_kernel<<<dim3(PIX / 64, CIN / 64, B_), 256>>>(input);

    cudaFuncSetAttribute(conv_kernel, cudaFuncAttributeMaxDynamicSharedMemorySize, DSMEM);
    conv_kernel<<<dim3(16, 4, B_), 256, DSMEM>>>(out);
}

// round 10
// speedup vs baseline: 6.8484x; 1.0503x over previous
#include <cuda_runtime.h>
#include <cuda_fp16.h>
#include <cstdint>
#include <math.h>

// ---------------- problem constants ----------------
#define B_    16
#define CIN   512
#define COUT  512
#define HH    64
#define WW    64
#define PIX   4096
#define SD    512
#define EPSV  1e-8f
#define MOD_SCALE_F  0.04419417382415922f   // 1/sqrt(512)
#define CONV_SCALE_F 0.014731391274719738f  // 1/sqrt(512*9)
#define CS2_F        0.00021701388888888888f

// ---------------- tiling ----------------
// CTA: M=128 couts x N=256 pixels (4 image rows), K-chunk=64 cins, 72 chunks
#define NCH   72
#define ROWB  144                // padded smem row bytes (128B data + 16B pad)
#define A_O   0
#define B_O   18432              // A: 128 rows * 144B
#define SSTAGE 55296             // A 18432 | B 36864 (256 rows * 144B)
#define NSTG  4
#define DSMEM (NSTG * SSTAGE)    // 221184 B

// ---------------- scratch ----------------
__device__ float g_s[B_ * CIN];
__device__ float g_wsq[COUT * CIN];
__device__ float g_demod[B_ * COUT];
__device__ __half g_xh[(size_t)B_ * PIX * CIN];   // [b][pixel][ci]  (x * s, fp16)
__device__ __half g_wh[(size_t)COUT * 9 * CIN];   // [cout][tap][ci] (fp16)

// ---------------- PTX helpers (baseline PTX, sm_80-class) ----------------
__device__ __forceinline__ uint32_t smem_u32(const void* p) {
    uint32_t a;
    asm("{ .reg .u64 t; cvta.to.shared.u64 t, %1; cvt.u32.u64 %0, t; }" : "=r"(a) : "l"(p));
    return a;
}
__device__ __forceinline__ void cpa16(uint32_t dst, const void* src, int srcsize) {
    asm volatile("cp.async.cg.shared.global [%0], [%1], 16, %2;\n"
                 :: "r"(dst), "l"(src), "r"(srcsize) : "memory");
}
#define CP_COMMIT() asm volatile("cp.async.commit_group;" ::: "memory")
#define CP_WAIT2()  asm volatile("cp.async.wait_group 2;" ::: "memory")
#define CP_WAIT1()  asm volatile("cp.async.wait_group 1;" ::: "memory")
#define CP_WAIT0()  asm volatile("cp.async.wait_group 0;" ::: "memory")

#define LDSM4(r, addr) \
    asm volatile("ldmatrix.sync.aligned.m8n8.x4.shared.b16 {%0,%1,%2,%3}, [%4];" \
        : "=r"((r)[0]), "=r"((r)[1]), "=r"((r)[2]), "=r"((r)[3]) : "r"(addr))

#define MMA16816(acc, a, b0, b1) \
    asm volatile("mma.sync.aligned.m16n8k16.row.col.f32.f16.f16.f32 " \
        "{%0,%1,%2,%3},{%4,%5,%6,%7},{%8,%9},{%0,%1,%2,%3};" \
        : "+f"((acc)[0]), "+f"((acc)[1]), "+f"((acc)[2]), "+f"((acc)[3]) \
        : "r"((a)[0]), "r"((a)[1]), "r"((a)[2]), "r"((a)[3]), "r"(b0), "r"(b1))

// ---------------- preprocessing kernels ----------------
__global__ void modulate_kernel(const float* __restrict__ style,
                                const float* __restrict__ mw,
                                const float* __restrict__ mb) {
    int warp = (blockIdx.x * blockDim.x + threadIdx.x) >> 5;
    int lane = threadIdx.x & 31;
    if (warp >= B_ * CIN) return;
    int b = warp / CIN, cin = warp % CIN;
    const float* srow = style + (size_t)b * SD;
    const float* wrow = mw + (size_t)cin * SD;
    float sum = 0.f;
    #pragma unroll 4
    for (int j = lane; j < SD; j += 32) sum += srow[j] * wrow[j];
    #pragma unroll
    for (int o = 16; o; o >>= 1) sum += __shfl_xor_sync(0xffffffffu, sum, o);
    if (lane == 0) g_s[warp] = sum * MOD_SCALE_F + mb[cin];
}

// weights: per (cout, cin) thread: read 9 taps, write fp16 [cout][tap][cin] + wsq
__global__ void wprep_kernel(const float* __restrict__ cw) {
    int idx = blockIdx.x * blockDim.x + threadIdx.x;
    if (idx >= COUT * CIN) return;
    int cout = idx / CIN;
    int ci = idx - cout * CIN;
    const float* p = cw + (size_t)idx * 9;
    float sq = 0.f;
    #pragma unroll
    for (int k = 0; k < 9; k++) {
        float v = p[k];
        sq += v * v;
        g_wh[((size_t)cout * 9 + k) * CIN + ci] = __float2half_rn(v);
    }
    g_wsq[idx] = sq;
}

__global__ void demod_kernel() {
    int warp = (blockIdx.x * blockDim.x + threadIdx.x) >> 5;
    int lane = threadIdx.x & 31;
    if (warp >= B_ * COUT) return;
    int b = warp / COUT, cout = warp % COUT;
    const float* srow = g_s + (size_t)b * CIN;
    const float* wrow = g_wsq + (size_t)cout * CIN;
    float sum = 0.f;
    #pragma unroll 4
    for (int cin = lane; cin < CIN; cin += 32) {
        float s = srow[cin];
        sum += s * s * wrow[cin];
    }
    #pragma unroll
    for (int o = 16; o; o >>= 1) sum += __shfl_xor_sync(0xffffffffu, sum, o);
    if (lane == 0) g_demod[warp] = rsqrtf(sum * CS2_F + EPSV);
}

// input: [b][ci][p] * s[b][ci] -> channel-last fp16 [b][p][ci]
__global__ __launch_bounds__(256) void xprep_kernel(const float* __restrict__ x) {
    __shared__ float tile[64][65];
    int b = blockIdx.z, ci0 = blockIdx.y * 64, p0 = blockIdx.x * 64;
    int tid = threadIdx.x;
    int j = tid & 63, i0 = tid >> 6;
    #pragma unroll
    for (int ii = 0; ii < 16; ii++) {
        int ci = i0 + ii * 4;
        float s = g_s[b * CIN + ci0 + ci];
        tile[ci][j] = x[((size_t)(b * CIN + ci0 + ci)) * PIX + p0 + j] * s;
    }
    __syncthreads();
    #pragma unroll
    for (int ii = 0; ii < 16; ii++) {
        int pl = i0 + ii * 4;
        g_xh[((size_t)b * PIX + p0 + pl) * CIN + ci0 + j] = __float2half_rn(tile[j][pl]);
    }
}

// ---------------- main HMMA implicit-GEMM conv (128x256 CTA, 64x64 warp, k64)
__global__ __launch_bounds__(256, 1) void conv_kernel(float* __restrict__ out) {
    extern __shared__ char smem[];
    const uint32_t sb = smem_u32(smem);
    const int tid = threadIdx.x;
    const int ptile = blockIdx.x;            // 16 pixel tiles (256 px = 4 rows)
    const int cout0 = blockIdx.y * 128;      // 4 cout tiles
    const int b = blockIdx.z;
    const int warp = tid >> 5, lane = tid & 31;
    const int mw = warp & 1;                 // 2 m-warps (64 couts each)
    const int nw = warp >> 1;                // 4 n-warps (64 pixels each)

    // staging: every thread stages B row tid; threads 0-127 also stage A row tid
    const bool isA = tid < 128;
    const int py0 = (ptile * 256 + tid) >> 6;
    const int px0 = tid & 63;

    float acc[4][8][4];
    #pragma unroll
    for (int mt = 0; mt < 4; mt++)
        #pragma unroll
        for (int nt = 0; nt < 8; nt++)
            #pragma unroll
            for (int r = 0; r < 4; r++) acc[mt][nt][r] = 0.f;

    #define FETCH(i) do {                                                        \
        int _tap = (i) >> 3;                                                     \
        int _kc  = ((i) & 7) << 6;                                               \
        uint32_t _stb = sb + ((i) % NSTG) * SSTAGE;                              \
        if (isA) {                                                               \
            const __half* _as = g_wh + ((size_t)(cout0 + tid) * 9 + _tap) * CIN + _kc; \
            uint32_t _ad = _stb + A_O + tid * ROWB;                              \
            _Pragma("unroll")                                                    \
            for (int _s = 0; _s < 8; _s++)                                       \
                cpa16(_ad + _s * 16, _as + _s * 8, 16);                          \
        }                                                                        \
        {                                                                        \
            int _dy = _tap / 3, _dx = _tap - _dy * 3;                            \
            int _py = py0 + _dy - 1, _px = px0 + _dx - 1;                        \
            bool _ok = ((unsigned)_py < HH) && ((unsigned)_px < WW);             \
            size_t _xo = _ok ? (((size_t)(b * PIX + _py * WW + _px)) * CIN + _kc) : 0; \
            int _sz = _ok ? 16 : 0;                                              \
            const __half* _bs = g_xh + _xo;                                      \
            uint32_t _bd = _stb + B_O + tid * ROWB;                              \
            _Pragma("unroll")                                                    \
            for (int _s = 0; _s < 8; _s++)                                       \
                cpa16(_bd + _s * 16, _bs + _s * 8, _sz);                         \
        }                                                                        \
        CP_COMMIT();                                                             \
    } while (0)

    FETCH(0);
    FETCH(1);
    FETCH(2);

    // per-lane ldmatrix address components (proven layout)
    const int am = mw * 64 + (lane & 7) + ((lane >> 3) & 1) * 8;   // + mt*16
    const uint32_t akb = ((lane >> 4) & 1) * 16;                   // + kk*32
    const int bn = nw * 64 + ((lane >> 4) & 1) * 8 + (lane & 7);   // + pr*16
    const uint32_t bkb = ((lane >> 3) & 1) * 16;                   // + kk*32

    for (int i = 0; i < NCH; i++) {
        if (i <= NCH - 3)      CP_WAIT2();
        else if (i == NCH - 2) CP_WAIT1();
        else                   CP_WAIT0();
        __syncthreads();
        if (i + 3 < NCH) FETCH(i + 3);

        const uint32_t stb = sb + (i % NSTG) * SSTAGE;
        #pragma unroll
        for (int kk = 0; kk < 4; kk++) {
            uint32_t a[4][4], bfr[4][4];
            #pragma unroll
            for (int mt = 0; mt < 4; mt++)
                LDSM4(a[mt], stb + A_O + (uint32_t)(am + mt * 16) * ROWB + kk * 32 + akb);
            #pragma unroll
            for (int pr = 0; pr < 4; pr++)
                LDSM4(bfr[pr], stb + B_O + (uint32_t)(bn + pr * 16) * ROWB + kk * 32 + bkb);
            #pragma unroll
            for (int mt = 0; mt < 4; mt++)
                #pragma unroll
                for (int nt = 0; nt < 8; nt++) {
                    const int pr = nt >> 1, o = (nt & 1) * 2;
                    MMA16816(acc[mt][nt], a[mt], bfr[pr][o], bfr[pr][o + 1]);
                }
        }
    }

    // ---- epilogue: scale by demod*CONV_SCALE, write float2 ----
    const int r4 = lane >> 2, t4 = lane & 3;
    #pragma unroll
    for (int mt = 0; mt < 4; mt++) {
        const int c0 = cout0 + mw * 64 + mt * 16 + r4;
        const float d0 = g_demod[b * COUT + c0] * CONV_SCALE_F;
        const float d1 = g_demod[b * COUT + c0 + 8] * CONV_SCALE_F;
        #pragma unroll
        for (int nt = 0; nt < 8; nt++) {
            const int pix = ptile * 256 + nw * 64 + nt * 8 + t4 * 2;
            float* p0 = out + ((size_t)(b * COUT + c0)) * PIX + pix;
            float* p1 = out + ((size_t)(b * COUT + c0 + 8)) * PIX + pix;
            float2 v0, v1;
            v0.x = acc[mt][nt][0] * d0; v0.y = acc[mt][nt][1] * d0;
            v1.x = acc[mt][nt][2] * d1; v1.y = acc[mt][nt][3] * d1;
            *(float2*)p0 = v0;
            *(float2*)p1 = v1;
        }
    }
}

// ---------------- launch ----------------
extern "C" void kernel_launch(void* const* d_in, const int* in_sizes, int n_in,
                              void* d_out, int out_size) {
    const float* input  = (const float*)d_in[0];  // [16,512,64,64]
    const float* style  = (const float*)d_in[1];  // [16,512]
    const float* conv_w = (const float*)d_in[2];  // [1,512,512,3,3]
    const float* mod_w  = (const float*)d_in[3];  // [512,512]
    const float* mod_b  = (const float*)d_in[4];  // [512]
    float* out = (float*)d_out;                   // [16,512,64,64]

    modulate_kernel<<<1024, 256>>>(style, mod_w, mod_b);
    wprep_kernel<<<(COUT * CIN + 255) / 256, 256>>>(conv_w);
    demod_kernel<<<1024, 256>>>();
    xprep_kernel<<<dim3(PIX / 64, CIN / 64, B_), 256>>>(input);

    cudaFuncSetAttribute(conv_kernel, cudaFuncAttributeMaxDynamicSharedMemorySize, DSMEM);
    conv_kernel<<<dim3(16, 4, B_), 256, DSMEM>>>(out);
}